// round 3
// baseline (speedup 1.0000x reference)
#include <cuda_runtime.h>

#define DD 128
#define HH 160
#define WW 160
#define W4 40                      // WW / 4
#define HWX (HH * WW)              // 25600
#define HW4 (HH * W4)              // 6400 float4 per slice
#define NV  (DD * HWX)             // 3276800
#define NV4 (DD * HW4)             // 819200 float4 per channel
#define NITER 10

#define GW0 0.40261995f
#define GW1 0.24420134f
#define GW2 0.05448868f

#define IROWS 32
#define NT_HW 5                    // 160 / 32
#define SROWS 38                   // sum rows: h0-3 .. h0+34
#define FROWS 36                   // force rows: h0-2 .. h0+33

// Scratch (device globals: allocation-free)
static __device__ float g_sum[NV];
static __device__ float g_diff[NV];
static __device__ float g_vfA[3 * NV];
static __device__ float g_vfC[3 * NV];

__device__ __forceinline__ float movAt(const float* __restrict__ m, int d, int h, int w) {
    if ((unsigned)d >= DD || (unsigned)h >= HH || (unsigned)w >= WW) return 0.0f;
    return __ldg(m + (d * HH + h) * WW + w);
}

// ---------------------------------------------------------------------------
// Iteration 0: vf == 0 so warped == mov.  sum/diff elementwise.
// ---------------------------------------------------------------------------
__global__ void __launch_bounds__(256) sumdiff0_kernel(const float4* __restrict__ mov,
                                                       const float4* __restrict__ fix,
                                                       float4* __restrict__ sum,
                                                       float4* __restrict__ diff) {
    int i = blockIdx.x * 256 + threadIdx.x;
    if (i >= NV4) return;
    float4 m = mov[i], f = fix[i];
    sum[i]  = make_float4(m.x + f.x, m.y + f.y, m.z + f.z, m.w + f.w);
    diff[i] = make_float4(m.x - f.x, m.y - f.y, m.z - f.z, m.w - f.w);
}

// ---------------------------------------------------------------------------
// Warp: trilinear sample of mov at grid+vf; emits sum & diff vs fix
// ---------------------------------------------------------------------------
__global__ void __launch_bounds__(256) warp_kernel4(const float* __restrict__ mov,
                                                    const float4* __restrict__ fix,
                                                    const float4* __restrict__ vf,
                                                    float4* __restrict__ sum,
                                                    float4* __restrict__ diff) {
    int i4 = blockIdx.x * 256 + threadIdx.x;
    if (i4 >= NV4) return;
    int w4 = i4 % W4;
    int h  = (i4 / W4) % HH;
    int d  = i4 / HW4;

    float4 v0 = vf[i4], v1 = vf[NV4 + i4], v2 = vf[2 * NV4 + i4];
    float4 fx = fix[i4];
    float4 s, df;

    #pragma unroll
    for (int j = 0; j < 4; ++j) {
        float cd = (float)d        + ((const float*)&v0)[j];
        float ch = (float)h        + ((const float*)&v1)[j];
        float cw = (float)(w4*4+j) + ((const float*)&v2)[j];

        float fd = floorf(cd), fh = floorf(ch), fw = floorf(cw);
        float td = cd - fd, th = ch - fh, tw = cw - fw;
        int d0 = (int)fd, h0 = (int)fh, w0 = (int)fw;

        float c00 = movAt(mov, d0,   h0,   w0) * (1.f-tw) + movAt(mov, d0,   h0,   w0+1) * tw;
        float c01 = movAt(mov, d0,   h0+1, w0) * (1.f-tw) + movAt(mov, d0,   h0+1, w0+1) * tw;
        float c10 = movAt(mov, d0+1, h0,   w0) * (1.f-tw) + movAt(mov, d0+1, h0,   w0+1) * tw;
        float c11 = movAt(mov, d0+1, h0+1, w0) * (1.f-tw) + movAt(mov, d0+1, h0+1, w0+1) * tw;

        float wv = (c00*(1.f-th) + c01*th) * (1.f-td) + (c10*(1.f-th) + c11*th) * td;
        float fv = ((const float*)&fx)[j];
        ((float*)&s)[j]  = wv + fv;
        ((float*)&df)[j] = wv - fv;
    }
    sum[i4]  = s;
    diff[i4] = df;
}

// ---------------------------------------------------------------------------
// Fused: demons force + W-smooth + H-smooth, per (d, h-tile) block, 3 channels.
// smem layout: s_sum[38*40] | s_scale[36*40] | s_f[36*40] | s_t[36*40]
// ---------------------------------------------------------------------------
__global__ void __launch_bounds__(256) fused_force_hw_kernel(const float4* __restrict__ sum,
                                                             const float4* __restrict__ diff,
                                                             const float4* __restrict__ vf_in,
                                                             float4* __restrict__ out) {
    extern __shared__ float4 sm[];
    float4* s_sum   = sm;                       // SROWS*W4
    float4* s_scale = s_sum + SROWS * W4;       // FROWS*W4
    float4* s_f     = s_scale + FROWS * W4;
    float4* s_t     = s_f + FROWS * W4;

    int d  = blockIdx.x % DD;
    int ht = blockIdx.x / DD;
    int h0 = ht * IROWS;
    const float4 z4 = make_float4(0.f, 0.f, 0.f, 0.f);

    const float4* sumd = sum + (size_t)d * HW4;

    // Load sum tile rows hg = h0-3 .. h0+34 (zero outside H)
    for (int t = threadIdx.x; t < SROWS * W4; t += 256) {
        int r = t / W4, cc = t % W4;
        int hg = h0 - 3 + r;
        s_sum[t] = ((unsigned)hg < HH) ? sumd[hg * W4 + cc] : z4;
    }
    __syncthreads();

    // Compute demon scale for force rows hg = h0-2 .. h0+33
    for (int t = threadIdx.x; t < FROWS * W4; t += 256) {
        int r = t / W4, cc = t % W4;
        int hg = h0 - 2 + r;
        if ((unsigned)hg >= HH) { s_scale[t] = z4; continue; }
        int sr = r + 1;  // center row in s_sum

        float4 m  = s_sum[sr * W4 + cc];
        float4 l  = (cc > 0)      ? s_sum[sr * W4 + cc - 1] : z4;
        float4 rr = (cc < W4 - 1) ? s_sum[sr * W4 + cc + 1] : z4;
        float4 up = s_sum[(sr - 1) * W4 + cc];
        float4 dn = s_sum[(sr + 1) * W4 + cc];
        float4 fr = (d > 0)      ? sum[(size_t)(d - 1) * HW4 + hg * W4 + cc] : z4;
        float4 bk = (d < DD - 1) ? sum[(size_t)(d + 1) * HW4 + hg * W4 + cc] : z4;
        float4 dv = diff[(size_t)d * HW4 + hg * W4 + cc];

        float4 sc;
        #pragma unroll
        for (int j = 0; j < 4; ++j) {
            int w = cc * 4 + j;
            float mj = ((const float*)&m)[j];

            float left  = (j > 0) ? ((const float*)&m)[j-1] : l.w;
            float right = (j < 3) ? ((const float*)&m)[j+1] : rr.x;
            float g2 = (w == 0) ? (right - mj) : (w == WW-1) ? (mj - left) : 0.5f*(right - left);

            float uj = ((const float*)&up)[j], dj = ((const float*)&dn)[j];
            float g1 = (hg == 0) ? (dj - mj) : (hg == HH-1) ? (mj - uj) : 0.5f*(dj - uj);

            float fj = ((const float*)&fr)[j], bj = ((const float*)&bk)[j];
            float g0 = (d == 0) ? (bj - mj) : (d == DD-1) ? (mj - fj) : 0.5f*(bj - fj);

            float dvj = ((const float*)&dv)[j];
            float denom = g0*g0 + g1*g1 + g2*g2 + dvj*dvj;
            ((float*)&sc)[j] = (denom > 1e-6f) ? (-dvj / denom) : 0.0f;
        }
        s_scale[t] = sc;
    }
    __syncthreads();

    for (int c = 0; c < 3; ++c) {
        // Force for channel c: f = vf + scale * g_c  (zero outside H range)
        for (int t = threadIdx.x; t < FROWS * W4; t += 256) {
            int r = t / W4, cc = t % W4;
            int hg = h0 - 2 + r;
            if ((unsigned)hg >= HH) { s_f[t] = z4; continue; }
            int sr = r + 1;

            float4 m = s_sum[sr * W4 + cc];
            float4 g;
            if (c == 0) {
                float4 fr = (d > 0)      ? sum[(size_t)(d - 1) * HW4 + hg * W4 + cc] : z4;
                float4 bk = (d < DD - 1) ? sum[(size_t)(d + 1) * HW4 + hg * W4 + cc] : z4;
                #pragma unroll
                for (int j = 0; j < 4; ++j) {
                    float mj = ((const float*)&m)[j];
                    float fj = ((const float*)&fr)[j], bj = ((const float*)&bk)[j];
                    ((float*)&g)[j] = (d == 0) ? (bj - mj) : (d == DD-1) ? (mj - fj) : 0.5f*(bj - fj);
                }
            } else if (c == 1) {
                float4 up = s_sum[(sr - 1) * W4 + cc];
                float4 dn = s_sum[(sr + 1) * W4 + cc];
                #pragma unroll
                for (int j = 0; j < 4; ++j) {
                    float mj = ((const float*)&m)[j];
                    float uj = ((const float*)&up)[j], dj = ((const float*)&dn)[j];
                    ((float*)&g)[j] = (hg == 0) ? (dj - mj) : (hg == HH-1) ? (mj - uj) : 0.5f*(dj - uj);
                }
            } else {
                float4 l  = (cc > 0)      ? s_sum[sr * W4 + cc - 1] : z4;
                float4 rr = (cc < W4 - 1) ? s_sum[sr * W4 + cc + 1] : z4;
                #pragma unroll
                for (int j = 0; j < 4; ++j) {
                    int w = cc * 4 + j;
                    float mj = ((const float*)&m)[j];
                    float left  = (j > 0) ? ((const float*)&m)[j-1] : l.w;
                    float right = (j < 3) ? ((const float*)&m)[j+1] : rr.x;
                    ((float*)&g)[j] = (w == 0) ? (right - mj) : (w == WW-1) ? (mj - left) : 0.5f*(right - left);
                }
            }

            float4 sc = s_scale[t];
            float4 v  = vf_in[(size_t)c * NV4 + (size_t)d * HW4 + hg * W4 + cc];
            s_f[t] = make_float4(v.x + sc.x * g.x, v.y + sc.y * g.y,
                                 v.z + sc.z * g.z, v.w + sc.w * g.w);
        }
        __syncthreads();

        // W-pass
        for (int t = threadIdx.x; t < FROWS * W4; t += 256) {
            int cc = t % W4;
            float4 m = s_f[t];
            float4 l = (cc > 0)      ? s_f[t - 1] : z4;
            float4 r = (cc < W4 - 1) ? s_f[t + 1] : z4;
            float4 o;
            o.x = GW2*l.z + GW1*l.w + GW0*m.x + GW1*m.y + GW2*m.z;
            o.y = GW2*l.w + GW1*m.x + GW0*m.y + GW1*m.z + GW2*m.w;
            o.z = GW2*m.x + GW1*m.y + GW0*m.z + GW1*m.w + GW2*r.x;
            o.w = GW2*m.y + GW1*m.z + GW0*m.w + GW1*r.x + GW2*r.y;
            s_t[t] = o;
        }
        __syncthreads();

        // H-pass + store 32 interior rows
        for (int t = threadIdx.x; t < IROWS * W4; t += 256) {
            int r = t / W4 + 2, cc = t % W4;
            float4 a = s_t[(r - 2) * W4 + cc];
            float4 b = s_t[(r - 1) * W4 + cc];
            float4 m = s_t[r * W4 + cc];
            float4 e = s_t[(r + 1) * W4 + cc];
            float4 f = s_t[(r + 2) * W4 + cc];
            float4 o;
            o.x = GW2*(a.x + f.x) + GW1*(b.x + e.x) + GW0*m.x;
            o.y = GW2*(a.y + f.y) + GW1*(b.y + e.y) + GW0*m.y;
            o.z = GW2*(a.z + f.z) + GW1*(b.z + e.z) + GW0*m.z;
            o.w = GW2*(a.w + f.w) + GW1*(b.w + e.w) + GW0*m.w;
            out[(size_t)c * NV4 + (size_t)d * HW4 + (h0 + r - 2) * W4 + cc] = o;
        }
        __syncthreads();
    }
}

// ---------------------------------------------------------------------------
// D-axis smoothing, sliding register window (16 outputs/thread)
// ---------------------------------------------------------------------------
#define DSEG 16
#define NDSEG (DD / DSEG)   // 8

__global__ void __launch_bounds__(256) smoothD_slide(const float4* __restrict__ in,
                                                     float4* __restrict__ out) {
    int gid = blockIdx.x * 256 + threadIdx.x;   // < 3 * NDSEG * HW4
    int col = gid % HW4;
    int seg = (gid / HW4) % NDSEG;
    int c   = gid / (HW4 * NDSEG);
    const float4 z4 = make_float4(0.f, 0.f, 0.f, 0.f);

    const float4* p = in  + (size_t)c * NV4 + col;
    float4*       q = out + (size_t)c * NV4 + col;
    int d0 = seg * DSEG;

    float4 x0 = (d0 - 2 >= 0) ? p[(size_t)(d0 - 2) * HW4] : z4;
    float4 x1 = (d0 - 1 >= 0) ? p[(size_t)(d0 - 1) * HW4] : z4;
    float4 x2 = p[(size_t)d0 * HW4];
    float4 x3 = p[(size_t)(d0 + 1) * HW4];
    float4 x4 = p[(size_t)(d0 + 2) * HW4];

    #pragma unroll
    for (int dd = 0; dd < DSEG; ++dd) {
        int d = d0 + dd;
        float4 o;
        o.x = GW2*(x0.x + x4.x) + GW1*(x1.x + x3.x) + GW0*x2.x;
        o.y = GW2*(x0.y + x4.y) + GW1*(x1.y + x3.y) + GW0*x2.y;
        o.z = GW2*(x0.z + x4.z) + GW1*(x1.z + x3.z) + GW0*x2.z;
        o.w = GW2*(x0.w + x4.w) + GW1*(x1.w + x3.w) + GW0*x2.w;
        q[(size_t)d * HW4] = o;
        x0 = x1; x1 = x2; x2 = x3; x3 = x4;
        x4 = (d + 3 < DD) ? p[(size_t)(d + 3) * HW4] : z4;
    }
}

extern "C" void kernel_launch(void* const* d_in, const int* in_sizes, int n_in,
                              void* d_out, int out_size) {
    const float* mov = (const float*)d_in[0];
    const float4* fix = (const float4*)d_in[1];
    float4* out4 = (float4*)d_out;

    float *vfA, *vfC, *sum, *diff;
    cudaGetSymbolAddress((void**)&vfA, g_vfA);
    cudaGetSymbolAddress((void**)&vfC, g_vfC);
    cudaGetSymbolAddress((void**)&sum, g_sum);
    cudaGetSymbolAddress((void**)&diff, g_diff);

    const int SMEM_FUSED = (SROWS * W4 + 3 * FROWS * W4) * sizeof(float4);  // 93440
    static int attr_set = 0;
    if (!attr_set) {
        cudaFuncSetAttribute(fused_force_hw_kernel,
                             cudaFuncAttributeMaxDynamicSharedMemorySize, SMEM_FUSED);
        attr_set = 1;
    }

    cudaMemsetAsync(vfA, 0, sizeof(float) * 3 * NV, 0);

    const int blocksN4 = NV4 / 256;          // 3200
    const int blocksF  = DD * NT_HW;         // 640
    const int blocksD  = (3 * NDSEG * HW4) / 256;  // 600

    for (int it = 0; it < NITER; ++it) {
        if (it == 0)
            sumdiff0_kernel<<<blocksN4, 256>>>((const float4*)mov, fix,
                                               (float4*)sum, (float4*)diff);
        else
            warp_kernel4<<<blocksN4, 256>>>(mov, fix, (const float4*)vfA,
                                            (float4*)sum, (float4*)diff);
        fused_force_hw_kernel<<<blocksF, 256, SMEM_FUSED>>>((const float4*)sum,
                                                            (const float4*)diff,
                                                            (const float4*)vfA,
                                                            (float4*)vfC);
        float4* dst = (it == NITER - 1) ? out4 : (float4*)vfA;
        smoothD_slide<<<blocksD, 256>>>((const float4*)vfC, dst);
    }
}

// round 4
// speedup vs baseline: 1.5995x; 1.5995x over previous
#include <cuda_runtime.h>

#define DD 128
#define HH 160
#define WW 160
#define W4 40                      // WW / 4
#define HWX (HH * WW)              // 25600
#define HW4 (HH * W4)              // 6400 float4 per slice
#define NV  (DD * HWX)             // 3276800
#define NV4 (DD * HW4)             // 819200 float4 per channel
#define NITER 10

// Gaussian weights: exp(-x^2/2), x in [-2,2], normalized
#define GW0 0.40261995f
#define GW1 0.24420134f
#define GW2 0.05448868f

// Scratch (device globals: allocation-free)
static __device__ float g_sum[NV];
static __device__ float g_diff[NV];
static __device__ float g_vfA[3 * NV];
static __device__ float g_vfB[3 * NV];
static __device__ float g_vfC[3 * NV];

__device__ __forceinline__ float movAt(const float* __restrict__ m, int d, int h, int w) {
    if ((unsigned)d >= DD || (unsigned)h >= HH || (unsigned)w >= WW) return 0.0f;
    return __ldg(m + (d * HH + h) * WW + w);
}

// ---------------------------------------------------------------------------
// Iteration 0: vf == 0 so warped == mov.  sum/diff elementwise.
// ---------------------------------------------------------------------------
__global__ void __launch_bounds__(256) sumdiff0_kernel(const float4* __restrict__ mov,
                                                       const float4* __restrict__ fix,
                                                       float4* __restrict__ sum,
                                                       float4* __restrict__ diff) {
    int i = blockIdx.x * 256 + threadIdx.x;
    if (i >= NV4) return;
    float4 m = mov[i], f = fix[i];
    sum[i]  = make_float4(m.x + f.x, m.y + f.y, m.z + f.z, m.w + f.w);
    diff[i] = make_float4(m.x - f.x, m.y - f.y, m.z - f.z, m.w - f.w);
}

// ---------------------------------------------------------------------------
// Warp: trilinear sample of mov at grid+vf; emits sum & diff vs fix.
// Fast path: single bounds test for the whole 2x2x2 cell.
// ---------------------------------------------------------------------------
__global__ void __launch_bounds__(256) warp_kernel4(const float* __restrict__ mov,
                                                    const float4* __restrict__ fix,
                                                    const float4* __restrict__ vf,
                                                    float4* __restrict__ sum,
                                                    float4* __restrict__ diff) {
    int i4 = blockIdx.x * 256 + threadIdx.x;
    if (i4 >= NV4) return;
    int w4 = i4 % W4;
    int h  = (i4 / W4) % HH;
    int d  = i4 / HW4;

    float4 v0 = vf[i4], v1 = vf[NV4 + i4], v2 = vf[2 * NV4 + i4];
    float4 fx = fix[i4];
    float4 s, df;

    #pragma unroll
    for (int j = 0; j < 4; ++j) {
        float cd = (float)d        + ((const float*)&v0)[j];
        float ch = (float)h        + ((const float*)&v1)[j];
        float cw = (float)(w4*4+j) + ((const float*)&v2)[j];

        float fd = floorf(cd), fh = floorf(ch), fw = floorf(cw);
        float td = cd - fd, th = ch - fh, tw = cw - fw;
        int d0 = (int)fd, h0 = (int)fh, w0 = (int)fw;

        float m000, m001, m010, m011, m100, m101, m110, m111;
        if ((unsigned)d0 < DD - 1 && (unsigned)h0 < HH - 1 && (unsigned)w0 < WW - 1) {
            const float* p = mov + (d0 * HH + h0) * WW + w0;
            m000 = __ldg(p);             m001 = __ldg(p + 1);
            m010 = __ldg(p + WW);        m011 = __ldg(p + WW + 1);
            m100 = __ldg(p + HWX);       m101 = __ldg(p + HWX + 1);
            m110 = __ldg(p + HWX + WW);  m111 = __ldg(p + HWX + WW + 1);
        } else {
            m000 = movAt(mov, d0,   h0,   w0);   m001 = movAt(mov, d0,   h0,   w0+1);
            m010 = movAt(mov, d0,   h0+1, w0);   m011 = movAt(mov, d0,   h0+1, w0+1);
            m100 = movAt(mov, d0+1, h0,   w0);   m101 = movAt(mov, d0+1, h0,   w0+1);
            m110 = movAt(mov, d0+1, h0+1, w0);   m111 = movAt(mov, d0+1, h0+1, w0+1);
        }

        float c00 = m000 * (1.f-tw) + m001 * tw;
        float c01 = m010 * (1.f-tw) + m011 * tw;
        float c10 = m100 * (1.f-tw) + m101 * tw;
        float c11 = m110 * (1.f-tw) + m111 * tw;
        float wv = (c00*(1.f-th) + c01*th) * (1.f-td) + (c10*(1.f-th) + c11*th) * td;
        float fv = ((const float*)&fx)[j];
        ((float*)&s)[j]  = wv + fv;
        ((float*)&df)[j] = wv - fv;
    }
    sum[i4]  = s;
    diff[i4] = df;
}

// ---------------------------------------------------------------------------
// Force: demons force + vf update (grad(warped)+grad(fix) == grad(sum))
// ---------------------------------------------------------------------------
__global__ void __launch_bounds__(256) force_kernel4(const float4* __restrict__ s,
                                                     const float4* __restrict__ diff,
                                                     const float4* __restrict__ vf_in,
                                                     float4* __restrict__ vf_out) {
    int i4 = blockIdx.x * 256 + threadIdx.x;
    if (i4 >= NV4) return;
    int w4 = i4 % W4;
    int h  = (i4 / W4) % HH;
    int d  = i4 / HW4;

    const float4 z4 = make_float4(0.f, 0.f, 0.f, 0.f);
    float4 sm = s[i4];
    float4 sl = (w4 > 0)      ? s[i4 - 1]   : z4;
    float4 sr = (w4 < W4 - 1) ? s[i4 + 1]   : z4;
    float4 su = (h  > 0)      ? s[i4 - W4]  : z4;
    float4 sd = (h  < HH - 1) ? s[i4 + W4]  : z4;
    float4 sf = (d  > 0)      ? s[i4 - HW4] : z4;
    float4 sb = (d  < DD - 1) ? s[i4 + HW4] : z4;
    float4 df4 = diff[i4];

    float4 v0 = vf_in[i4], v1 = vf_in[NV4 + i4], v2 = vf_in[2 * NV4 + i4];
    float4 o0, o1, o2;

    #pragma unroll
    for (int j = 0; j < 4; ++j) {
        int w = w4 * 4 + j;
        float smj = ((const float*)&sm)[j];

        float left  = (j > 0) ? ((const float*)&sm)[j-1] : sl.w;
        float right = (j < 3) ? ((const float*)&sm)[j+1] : sr.x;
        float g2 = (w == 0) ? (right - smj) : (w == WW-1) ? (smj - left) : 0.5f * (right - left);

        float up = ((const float*)&su)[j], dn = ((const float*)&sd)[j];
        float g1 = (h == 0) ? (dn - smj) : (h == HH-1) ? (smj - up) : 0.5f * (dn - up);

        float fr = ((const float*)&sf)[j], bk = ((const float*)&sb)[j];
        float g0 = (d == 0) ? (bk - smj) : (d == DD-1) ? (smj - fr) : 0.5f * (bk - fr);

        float dv = ((const float*)&df4)[j];
        float denom = g0*g0 + g1*g1 + g2*g2 + dv*dv;
        float scale = (denom > 1e-6f) ? (-dv / denom) : 0.0f;

        ((float*)&o0)[j] = ((const float*)&v0)[j] + scale * g0;
        ((float*)&o1)[j] = ((const float*)&v1)[j] + scale * g1;
        ((float*)&o2)[j] = ((const float*)&v2)[j] + scale * g2;
    }
    vf_out[i4]           = o0;
    vf_out[NV4 + i4]     = o1;
    vf_out[2 * NV4 + i4] = o2;
}

// ---------------------------------------------------------------------------
// Fused W+H Gaussian smoothing on one (channel, d, h-tile): smem slice tile.
// ---------------------------------------------------------------------------
#define TROWS 36
#define IROWS 32
#define NT_HW 5   // 160 / 32

__global__ void __launch_bounds__(256) smoothHW_kernel(const float4* __restrict__ in,
                                                       float4* __restrict__ out) {
    __shared__ float4 s0[TROWS * W4];
    __shared__ float4 s1[TROWS * W4];

    int b  = blockIdx.x;
    int ht = b % NT_HW;
    int d  = (b / NT_HW) % DD;
    int c  = b / (NT_HW * DD);
    int h0 = ht * IROWS;

    const float4* src = in  + (size_t)c * NV4 + (size_t)d * HW4;
    float4*       dst = out + (size_t)c * NV4 + (size_t)d * HW4;
    const float4 z4 = make_float4(0.f, 0.f, 0.f, 0.f);

    for (int t = threadIdx.x; t < TROWS * W4; t += 256) {
        int r  = t / W4;
        int cc = t % W4;
        int hg = h0 - 2 + r;
        s0[t] = ((unsigned)hg < HH) ? src[hg * W4 + cc] : z4;
    }
    __syncthreads();

    for (int t = threadIdx.x; t < TROWS * W4; t += 256) {
        int cc = t % W4;
        float4 m = s0[t];
        float4 l = (cc > 0)      ? s0[t - 1] : z4;
        float4 r = (cc < W4 - 1) ? s0[t + 1] : z4;
        float4 o;
        o.x = GW2*l.z + GW1*l.w + GW0*m.x + GW1*m.y + GW2*m.z;
        o.y = GW2*l.w + GW1*m.x + GW0*m.y + GW1*m.z + GW2*m.w;
        o.z = GW2*m.x + GW1*m.y + GW0*m.z + GW1*m.w + GW2*r.x;
        o.w = GW2*m.y + GW1*m.z + GW0*m.w + GW1*r.x + GW2*r.y;
        s1[t] = o;
    }
    __syncthreads();

    for (int t = threadIdx.x; t < IROWS * W4; t += 256) {
        int r  = t / W4 + 2;
        int cc = t % W4;
        float4 a = s1[(r - 2) * W4 + cc];
        float4 b2 = s1[(r - 1) * W4 + cc];
        float4 m = s1[r * W4 + cc];
        float4 e = s1[(r + 1) * W4 + cc];
        float4 f = s1[(r + 2) * W4 + cc];
        float4 o;
        o.x = GW2*(a.x + f.x) + GW1*(b2.x + e.x) + GW0*m.x;
        o.y = GW2*(a.y + f.y) + GW1*(b2.y + e.y) + GW0*m.y;
        o.z = GW2*(a.z + f.z) + GW1*(b2.z + e.z) + GW0*m.z;
        o.w = GW2*(a.w + f.w) + GW1*(b2.w + e.w) + GW0*m.w;
        dst[(h0 + r - 2) * W4 + cc] = o;
    }
}

// ---------------------------------------------------------------------------
// D-axis smoothing, sliding register window (16 outputs/thread)
// ---------------------------------------------------------------------------
#define DSEG 16
#define NDSEG (DD / DSEG)   // 8

__global__ void __launch_bounds__(256) smoothD_slide(const float4* __restrict__ in,
                                                     float4* __restrict__ out) {
    int gid = blockIdx.x * 256 + threadIdx.x;   // < 3 * NDSEG * HW4
    int col = gid % HW4;
    int seg = (gid / HW4) % NDSEG;
    int c   = gid / (HW4 * NDSEG);
    const float4 z4 = make_float4(0.f, 0.f, 0.f, 0.f);

    const float4* p = in  + (size_t)c * NV4 + col;
    float4*       q = out + (size_t)c * NV4 + col;
    int d0 = seg * DSEG;

    float4 x0 = (d0 - 2 >= 0) ? p[(size_t)(d0 - 2) * HW4] : z4;
    float4 x1 = (d0 - 1 >= 0) ? p[(size_t)(d0 - 1) * HW4] : z4;
    float4 x2 = p[(size_t)d0 * HW4];
    float4 x3 = p[(size_t)(d0 + 1) * HW4];
    float4 x4 = p[(size_t)(d0 + 2) * HW4];

    #pragma unroll
    for (int dd = 0; dd < DSEG; ++dd) {
        int d = d0 + dd;
        float4 o;
        o.x = GW2*(x0.x + x4.x) + GW1*(x1.x + x3.x) + GW0*x2.x;
        o.y = GW2*(x0.y + x4.y) + GW1*(x1.y + x3.y) + GW0*x2.y;
        o.z = GW2*(x0.z + x4.z) + GW1*(x1.z + x3.z) + GW0*x2.z;
        o.w = GW2*(x0.w + x4.w) + GW1*(x1.w + x3.w) + GW0*x2.w;
        q[(size_t)d * HW4] = o;
        x0 = x1; x1 = x2; x2 = x3; x3 = x4;
        x4 = (d + 3 < DD) ? p[(size_t)(d + 3) * HW4] : z4;
    }
}

extern "C" void kernel_launch(void* const* d_in, const int* in_sizes, int n_in,
                              void* d_out, int out_size) {
    const float* mov = (const float*)d_in[0];
    const float4* fix = (const float4*)d_in[1];
    float4* out4 = (float4*)d_out;

    float *vfA, *vfB, *vfC, *sum, *diff;
    cudaGetSymbolAddress((void**)&vfA, g_vfA);
    cudaGetSymbolAddress((void**)&vfB, g_vfB);
    cudaGetSymbolAddress((void**)&vfC, g_vfC);
    cudaGetSymbolAddress((void**)&sum, g_sum);
    cudaGetSymbolAddress((void**)&diff, g_diff);

    cudaMemsetAsync(vfA, 0, sizeof(float) * 3 * NV, 0);

    const int blocksN4  = NV4 / 256;                // 3200
    const int blocksHW  = 3 * DD * NT_HW;           // 1920
    const int blocksD   = (3 * NDSEG * HW4) / 256;  // 600

    for (int it = 0; it < NITER; ++it) {
        if (it == 0)
            sumdiff0_kernel<<<blocksN4, 256>>>((const float4*)mov, fix,
                                               (float4*)sum, (float4*)diff);
        else
            warp_kernel4<<<blocksN4, 256>>>(mov, fix, (const float4*)vfA,
                                            (float4*)sum, (float4*)diff);
        force_kernel4<<<blocksN4, 256>>>((const float4*)sum, (const float4*)diff,
                                         (const float4*)vfA, (float4*)vfB);
        smoothHW_kernel<<<blocksHW, 256>>>((const float4*)vfB, (float4*)vfC);
        float4* dst = (it == NITER - 1) ? out4 : (float4*)vfA;
        smoothD_slide<<<blocksD, 256>>>((const float4*)vfC, dst);
    }
}

// round 5
// speedup vs baseline: 1.7721x; 1.1079x over previous
#include <cuda_runtime.h>

#define DD 128
#define HH 160
#define WW 160
#define W4 40                      // WW / 4
#define HWX (HH * WW)              // 25600
#define HW4 (HH * W4)              // 6400 float4 per slice
#define NV  (DD * HWX)             // 3276800
#define NV4 (DD * HW4)             // 819200 float4 per channel
#define NITER 10

// Gaussian weights: exp(-x^2/2), x in [-2,2], normalized
#define GW0 0.40261995f
#define GW1 0.24420134f
#define GW2 0.05448868f

// Scratch (device globals: allocation-free)
static __device__ float g_sum[NV];
static __device__ float g_diff[NV];
static __device__ float g_vfA[3 * NV];
static __device__ float g_vfB[3 * NV];
static __device__ float g_vfC[3 * NV];

__device__ __forceinline__ float movAt(const float* __restrict__ m, int d, int h, int w) {
    if ((unsigned)d >= DD || (unsigned)h >= HH || (unsigned)w >= WW) return 0.0f;
    return __ldg(m + (d * HH + h) * WW + w);
}

// ---------------------------------------------------------------------------
// Iteration 0: vf == 0 so warped == mov.  sum/diff elementwise.
// ---------------------------------------------------------------------------
__global__ void __launch_bounds__(256) sumdiff0_kernel(const float4* __restrict__ mov,
                                                       const float4* __restrict__ fix,
                                                       float4* __restrict__ sum,
                                                       float4* __restrict__ diff) {
    int i = blockIdx.x * 256 + threadIdx.x;
    if (i >= NV4) return;
    float4 m = mov[i], f = fix[i];
    sum[i]  = make_float4(m.x + f.x, m.y + f.y, m.z + f.z, m.w + f.w);
    diff[i] = make_float4(m.x - f.x, m.y - f.y, m.z - f.z, m.w - f.w);
}

// ---------------------------------------------------------------------------
// Warp: trilinear sample of mov at grid+vf; emits sum & diff vs fix.
// Fast path: single bounds test for the whole 2x2x2 cell.
// ---------------------------------------------------------------------------
__global__ void __launch_bounds__(256) warp_kernel4(const float* __restrict__ mov,
                                                    const float4* __restrict__ fix,
                                                    const float4* __restrict__ vf,
                                                    float4* __restrict__ sum,
                                                    float4* __restrict__ diff) {
    int i4 = blockIdx.x * 256 + threadIdx.x;
    if (i4 >= NV4) return;
    int w4 = i4 % W4;
    int h  = (i4 / W4) % HH;
    int d  = i4 / HW4;

    float4 v0 = vf[i4], v1 = vf[NV4 + i4], v2 = vf[2 * NV4 + i4];
    float4 fx = fix[i4];
    float4 s, df;

    #pragma unroll
    for (int j = 0; j < 4; ++j) {
        float cd = (float)d        + ((const float*)&v0)[j];
        float ch = (float)h        + ((const float*)&v1)[j];
        float cw = (float)(w4*4+j) + ((const float*)&v2)[j];

        float fd = floorf(cd), fh = floorf(ch), fw = floorf(cw);
        float td = cd - fd, th = ch - fh, tw = cw - fw;
        int d0 = (int)fd, h0 = (int)fh, w0 = (int)fw;

        float m000, m001, m010, m011, m100, m101, m110, m111;
        if ((unsigned)d0 < DD - 1 && (unsigned)h0 < HH - 1 && (unsigned)w0 < WW - 1) {
            const float* p = mov + (d0 * HH + h0) * WW + w0;
            m000 = __ldg(p);             m001 = __ldg(p + 1);
            m010 = __ldg(p + WW);        m011 = __ldg(p + WW + 1);
            m100 = __ldg(p + HWX);       m101 = __ldg(p + HWX + 1);
            m110 = __ldg(p + HWX + WW);  m111 = __ldg(p + HWX + WW + 1);
        } else {
            m000 = movAt(mov, d0,   h0,   w0);   m001 = movAt(mov, d0,   h0,   w0+1);
            m010 = movAt(mov, d0,   h0+1, w0);   m011 = movAt(mov, d0,   h0+1, w0+1);
            m100 = movAt(mov, d0+1, h0,   w0);   m101 = movAt(mov, d0+1, h0,   w0+1);
            m110 = movAt(mov, d0+1, h0+1, w0);   m111 = movAt(mov, d0+1, h0+1, w0+1);
        }

        float c00 = m000 * (1.f-tw) + m001 * tw;
        float c01 = m010 * (1.f-tw) + m011 * tw;
        float c10 = m100 * (1.f-tw) + m101 * tw;
        float c11 = m110 * (1.f-tw) + m111 * tw;
        float wv = (c00*(1.f-th) + c01*th) * (1.f-td) + (c10*(1.f-th) + c11*th) * td;
        float fv = ((const float*)&fx)[j];
        ((float*)&s)[j]  = wv + fv;
        ((float*)&df)[j] = wv - fv;
    }
    sum[i4]  = s;
    diff[i4] = df;
}

// ---------------------------------------------------------------------------
// Force: demons force + vf update (grad(warped)+grad(fix) == grad(sum))
// ---------------------------------------------------------------------------
__global__ void __launch_bounds__(256) force_kernel4(const float4* __restrict__ s,
                                                     const float4* __restrict__ diff,
                                                     const float4* __restrict__ vf_in,
                                                     float4* __restrict__ vf_out) {
    int i4 = blockIdx.x * 256 + threadIdx.x;
    if (i4 >= NV4) return;
    int w4 = i4 % W4;
    int h  = (i4 / W4) % HH;
    int d  = i4 / HW4;

    const float4 z4 = make_float4(0.f, 0.f, 0.f, 0.f);
    float4 sm = s[i4];
    float4 sl = (w4 > 0)      ? s[i4 - 1]   : z4;
    float4 sr = (w4 < W4 - 1) ? s[i4 + 1]   : z4;
    float4 su = (h  > 0)      ? s[i4 - W4]  : z4;
    float4 sd = (h  < HH - 1) ? s[i4 + W4]  : z4;
    float4 sf = (d  > 0)      ? s[i4 - HW4] : z4;
    float4 sb = (d  < DD - 1) ? s[i4 + HW4] : z4;
    float4 df4 = diff[i4];

    float4 v0 = vf_in[i4], v1 = vf_in[NV4 + i4], v2 = vf_in[2 * NV4 + i4];
    float4 o0, o1, o2;

    #pragma unroll
    for (int j = 0; j < 4; ++j) {
        int w = w4 * 4 + j;
        float smj = ((const float*)&sm)[j];

        float left  = (j > 0) ? ((const float*)&sm)[j-1] : sl.w;
        float right = (j < 3) ? ((const float*)&sm)[j+1] : sr.x;
        float g2 = (w == 0) ? (right - smj) : (w == WW-1) ? (smj - left) : 0.5f * (right - left);

        float up = ((const float*)&su)[j], dn = ((const float*)&sd)[j];
        float g1 = (h == 0) ? (dn - smj) : (h == HH-1) ? (smj - up) : 0.5f * (dn - up);

        float fr = ((const float*)&sf)[j], bk = ((const float*)&sb)[j];
        float g0 = (d == 0) ? (bk - smj) : (d == DD-1) ? (smj - fr) : 0.5f * (bk - fr);

        float dv = ((const float*)&df4)[j];
        float denom = g0*g0 + g1*g1 + g2*g2 + dv*dv;
        float scale = (denom > 1e-6f) ? (-dv / denom) : 0.0f;

        ((float*)&o0)[j] = ((const float*)&v0)[j] + scale * g0;
        ((float*)&o1)[j] = ((const float*)&v1)[j] + scale * g1;
        ((float*)&o2)[j] = ((const float*)&v2)[j] + scale * g2;
    }
    vf_out[i4]           = o0;
    vf_out[NV4 + i4]     = o1;
    vf_out[2 * NV4 + i4] = o2;
}

// ---------------------------------------------------------------------------
// Fused W+H Gaussian smoothing, single smem buffer: W-pass computed straight
// from gmem (L1-resident re-reads), H-pass from smem. 23KB smem, 2 syncs.
// ---------------------------------------------------------------------------
#define TROWS 36
#define IROWS 32
#define NT_HW 5   // 160 / 32

__global__ void __launch_bounds__(256) smoothHW_kernel(const float4* __restrict__ in,
                                                       float4* __restrict__ out) {
    __shared__ float4 s1[TROWS * W4];

    int b  = blockIdx.x;
    int ht = b % NT_HW;
    int d  = (b / NT_HW) % DD;
    int c  = b / (NT_HW * DD);
    int h0 = ht * IROWS;

    const float4* src = in  + (size_t)c * NV4 + (size_t)d * HW4;
    float4*       dst = out + (size_t)c * NV4 + (size_t)d * HW4;
    const float4 z4 = make_float4(0.f, 0.f, 0.f, 0.f);

    // Load + W-pass fused: read m and its row neighbors from gmem (L1 hits)
    for (int t = threadIdx.x; t < TROWS * W4; t += 256) {
        int r  = t / W4;
        int cc = t % W4;
        int hg = h0 - 2 + r;
        float4 o;
        if ((unsigned)hg < HH) {
            const float4* row = src + hg * W4;
            float4 m = __ldg(row + cc);
            float4 l = (cc > 0)      ? __ldg(row + cc - 1) : z4;
            float4 r2 = (cc < W4 - 1) ? __ldg(row + cc + 1) : z4;
            o.x = GW2*l.z + GW1*l.w + GW0*m.x + GW1*m.y + GW2*m.z;
            o.y = GW2*l.w + GW1*m.x + GW0*m.y + GW1*m.z + GW2*m.w;
            o.z = GW2*m.x + GW1*m.y + GW0*m.z + GW1*m.w + GW2*r2.x;
            o.w = GW2*m.y + GW1*m.z + GW0*m.w + GW1*r2.x + GW2*r2.y;
        } else {
            o = z4;
        }
        s1[t] = o;
    }
    __syncthreads();

    // H-pass over 32 interior rows, write to global
    for (int t = threadIdx.x; t < IROWS * W4; t += 256) {
        int r  = t / W4 + 2;
        int cc = t % W4;
        float4 a = s1[(r - 2) * W4 + cc];
        float4 b2 = s1[(r - 1) * W4 + cc];
        float4 m = s1[r * W4 + cc];
        float4 e = s1[(r + 1) * W4 + cc];
        float4 f = s1[(r + 2) * W4 + cc];
        float4 o;
        o.x = GW2*(a.x + f.x) + GW1*(b2.x + e.x) + GW0*m.x;
        o.y = GW2*(a.y + f.y) + GW1*(b2.y + e.y) + GW0*m.y;
        o.z = GW2*(a.z + f.z) + GW1*(b2.z + e.z) + GW0*m.z;
        o.w = GW2*(a.w + f.w) + GW1*(b2.w + e.w) + GW0*m.w;
        dst[(h0 + r - 2) * W4 + cc] = o;
    }
}

// ---------------------------------------------------------------------------
// D-axis smoothing, sliding register window (8 outputs/thread -> 1200 blocks)
// ---------------------------------------------------------------------------
#define DSEG 8
#define NDSEG (DD / DSEG)   // 16

__global__ void __launch_bounds__(256) smoothD_slide(const float4* __restrict__ in,
                                                     float4* __restrict__ out) {
    int gid = blockIdx.x * 256 + threadIdx.x;   // < 3 * NDSEG * HW4
    int col = gid % HW4;
    int seg = (gid / HW4) % NDSEG;
    int c   = gid / (HW4 * NDSEG);
    const float4 z4 = make_float4(0.f, 0.f, 0.f, 0.f);

    const float4* p = in  + (size_t)c * NV4 + col;
    float4*       q = out + (size_t)c * NV4 + col;
    int d0 = seg * DSEG;

    float4 x0 = (d0 - 2 >= 0) ? p[(size_t)(d0 - 2) * HW4] : z4;
    float4 x1 = (d0 - 1 >= 0) ? p[(size_t)(d0 - 1) * HW4] : z4;
    float4 x2 = p[(size_t)d0 * HW4];
    float4 x3 = p[(size_t)(d0 + 1) * HW4];
    float4 x4 = p[(size_t)(d0 + 2) * HW4];

    #pragma unroll
    for (int dd = 0; dd < DSEG; ++dd) {
        int d = d0 + dd;
        float4 o;
        o.x = GW2*(x0.x + x4.x) + GW1*(x1.x + x3.x) + GW0*x2.x;
        o.y = GW2*(x0.y + x4.y) + GW1*(x1.y + x3.y) + GW0*x2.y;
        o.z = GW2*(x0.z + x4.z) + GW1*(x1.z + x3.z) + GW0*x2.z;
        o.w = GW2*(x0.w + x4.w) + GW1*(x1.w + x3.w) + GW0*x2.w;
        q[(size_t)d * HW4] = o;
        x0 = x1; x1 = x2; x2 = x3; x3 = x4;
        x4 = (d + 3 < DD) ? p[(size_t)(d + 3) * HW4] : z4;
    }
}

extern "C" void kernel_launch(void* const* d_in, const int* in_sizes, int n_in,
                              void* d_out, int out_size) {
    const float* mov = (const float*)d_in[0];
    const float4* fix = (const float4*)d_in[1];
    float4* out4 = (float4*)d_out;

    float *vfA, *vfB, *vfC, *sum, *diff;
    cudaGetSymbolAddress((void**)&vfA, g_vfA);
    cudaGetSymbolAddress((void**)&vfB, g_vfB);
    cudaGetSymbolAddress((void**)&vfC, g_vfC);
    cudaGetSymbolAddress((void**)&sum, g_sum);
    cudaGetSymbolAddress((void**)&diff, g_diff);

    cudaMemsetAsync(vfA, 0, sizeof(float) * 3 * NV, 0);

    const int blocksN4  = NV4 / 256;                // 3200
    const int blocksHW  = 3 * DD * NT_HW;           // 1920
    const int blocksD   = (3 * NDSEG * HW4) / 256;  // 1200

    for (int it = 0; it < NITER; ++it) {
        if (it == 0)
            sumdiff0_kernel<<<blocksN4, 256>>>((const float4*)mov, fix,
                                               (float4*)sum, (float4*)diff);
        else
            warp_kernel4<<<blocksN4, 256>>>(mov, fix, (const float4*)vfA,
                                            (float4*)sum, (float4*)diff);
        force_kernel4<<<blocksN4, 256>>>((const float4*)sum, (const float4*)diff,
                                         (const float4*)vfA, (float4*)vfB);
        smoothHW_kernel<<<blocksHW, 256>>>((const float4*)vfB, (float4*)vfC);
        float4* dst = (it == NITER - 1) ? out4 : (float4*)vfA;
        smoothD_slide<<<blocksD, 256>>>((const float4*)vfC, dst);
    }
}

// round 6
// speedup vs baseline: 1.8344x; 1.0352x over previous
#include <cuda_runtime.h>

#define DD 128
#define HH 160
#define WW 160
#define W4 40                      // WW / 4
#define HWX (HH * WW)              // 25600
#define HW4 (HH * W4)              // 6400 float4 per slice
#define NV  (DD * HWX)             // 3276800
#define NV4 (DD * HW4)             // 819200 float4 per channel
#define NITER 10

// Gaussian weights: exp(-x^2/2), x in [-2,2], normalized
#define GW0 0.40261995f
#define GW1 0.24420134f
#define GW2 0.05448868f

// Scratch (device globals: allocation-free)
static __device__ float g_sum[NV];
static __device__ float g_vfA[3 * NV];
static __device__ float g_vfB[3 * NV];
static __device__ float g_vfC[3 * NV];

__device__ __forceinline__ float movAt(const float* __restrict__ m, int d, int h, int w) {
    if ((unsigned)d >= DD || (unsigned)h >= HH || (unsigned)w >= WW) return 0.0f;
    return __ldg(m + (d * HH + h) * WW + w);
}

// ---------------------------------------------------------------------------
// Iteration 0: vf == 0 so warped == mov.  sum elementwise.
// ---------------------------------------------------------------------------
__global__ void __launch_bounds__(256) sum0_kernel(const float4* __restrict__ mov,
                                                   const float4* __restrict__ fix,
                                                   float4* __restrict__ sum) {
    int i = blockIdx.x * 256 + threadIdx.x;
    if (i >= NV4) return;
    float4 m = mov[i], f = fix[i];
    sum[i] = make_float4(m.x + f.x, m.y + f.y, m.z + f.z, m.w + f.w);
}

// ---------------------------------------------------------------------------
// Warp: trilinear sample of mov at grid+vf; emits sum = warped + fix.
// Fast path: single bounds test for the whole 2x2x2 cell.
// ---------------------------------------------------------------------------
__global__ void __launch_bounds__(256) warp_kernel4(const float* __restrict__ mov,
                                                    const float4* __restrict__ fix,
                                                    const float4* __restrict__ vf,
                                                    float4* __restrict__ sum) {
    int i4 = blockIdx.x * 256 + threadIdx.x;
    if (i4 >= NV4) return;
    int w4 = i4 % W4;
    int h  = (i4 / W4) % HH;
    int d  = i4 / HW4;

    float4 v0 = vf[i4], v1 = vf[NV4 + i4], v2 = vf[2 * NV4 + i4];
    float4 fx = fix[i4];
    float4 s;

    #pragma unroll
    for (int j = 0; j < 4; ++j) {
        float cd = (float)d        + ((const float*)&v0)[j];
        float ch = (float)h        + ((const float*)&v1)[j];
        float cw = (float)(w4*4+j) + ((const float*)&v2)[j];

        float fd = floorf(cd), fh = floorf(ch), fw = floorf(cw);
        float td = cd - fd, th = ch - fh, tw = cw - fw;
        int d0 = (int)fd, h0 = (int)fh, w0 = (int)fw;

        float m000, m001, m010, m011, m100, m101, m110, m111;
        if ((unsigned)d0 < DD - 1 && (unsigned)h0 < HH - 1 && (unsigned)w0 < WW - 1) {
            const float* p = mov + (d0 * HH + h0) * WW + w0;
            m000 = __ldg(p);             m001 = __ldg(p + 1);
            m010 = __ldg(p + WW);        m011 = __ldg(p + WW + 1);
            m100 = __ldg(p + HWX);       m101 = __ldg(p + HWX + 1);
            m110 = __ldg(p + HWX + WW);  m111 = __ldg(p + HWX + WW + 1);
        } else {
            m000 = movAt(mov, d0,   h0,   w0);   m001 = movAt(mov, d0,   h0,   w0+1);
            m010 = movAt(mov, d0,   h0+1, w0);   m011 = movAt(mov, d0,   h0+1, w0+1);
            m100 = movAt(mov, d0+1, h0,   w0);   m101 = movAt(mov, d0+1, h0,   w0+1);
            m110 = movAt(mov, d0+1, h0+1, w0);   m111 = movAt(mov, d0+1, h0+1, w0+1);
        }

        float c00 = m000 * (1.f-tw) + m001 * tw;
        float c01 = m010 * (1.f-tw) + m011 * tw;
        float c10 = m100 * (1.f-tw) + m101 * tw;
        float c11 = m110 * (1.f-tw) + m111 * tw;
        float wv = (c00*(1.f-th) + c01*th) * (1.f-td) + (c10*(1.f-th) + c11*th) * td;
        ((float*)&s)[j] = wv + ((const float*)&fx)[j];
    }
    sum[i4] = s;
}

// ---------------------------------------------------------------------------
// Force: demons force + vf update.
// grad(warped)+grad(fix) == grad(sum);  diff = warped - fix = sum - 2*fix.
// ---------------------------------------------------------------------------
__global__ void __launch_bounds__(256) force_kernel4(const float4* __restrict__ s,
                                                     const float4* __restrict__ fix,
                                                     const float4* __restrict__ vf_in,
                                                     float4* __restrict__ vf_out) {
    int i4 = blockIdx.x * 256 + threadIdx.x;
    if (i4 >= NV4) return;
    int w4 = i4 % W4;
    int h  = (i4 / W4) % HH;
    int d  = i4 / HW4;

    const float4 z4 = make_float4(0.f, 0.f, 0.f, 0.f);
    float4 sm = s[i4];
    float4 sl = (w4 > 0)      ? s[i4 - 1]   : z4;
    float4 sr = (w4 < W4 - 1) ? s[i4 + 1]   : z4;
    float4 su = (h  > 0)      ? s[i4 - W4]  : z4;
    float4 sd = (h  < HH - 1) ? s[i4 + W4]  : z4;
    float4 sf = (d  > 0)      ? s[i4 - HW4] : z4;
    float4 sb = (d  < DD - 1) ? s[i4 + HW4] : z4;
    float4 fx = fix[i4];

    float4 v0 = vf_in[i4], v1 = vf_in[NV4 + i4], v2 = vf_in[2 * NV4 + i4];
    float4 o0, o1, o2;

    #pragma unroll
    for (int j = 0; j < 4; ++j) {
        int w = w4 * 4 + j;
        float smj = ((const float*)&sm)[j];

        float left  = (j > 0) ? ((const float*)&sm)[j-1] : sl.w;
        float right = (j < 3) ? ((const float*)&sm)[j+1] : sr.x;
        float g2 = (w == 0) ? (right - smj) : (w == WW-1) ? (smj - left) : 0.5f * (right - left);

        float up = ((const float*)&su)[j], dn = ((const float*)&sd)[j];
        float g1 = (h == 0) ? (dn - smj) : (h == HH-1) ? (smj - up) : 0.5f * (dn - up);

        float fr = ((const float*)&sf)[j], bk = ((const float*)&sb)[j];
        float g0 = (d == 0) ? (bk - smj) : (d == DD-1) ? (smj - fr) : 0.5f * (bk - fr);

        float dv = smj - 2.0f * ((const float*)&fx)[j];   // warped - fix
        float denom = g0*g0 + g1*g1 + g2*g2 + dv*dv;
        float scale = (denom > 1e-6f) ? __fdividef(-dv, denom) : 0.0f;

        ((float*)&o0)[j] = ((const float*)&v0)[j] + scale * g0;
        ((float*)&o1)[j] = ((const float*)&v1)[j] + scale * g1;
        ((float*)&o2)[j] = ((const float*)&v2)[j] + scale * g2;
    }
    vf_out[i4]           = o0;
    vf_out[NV4 + i4]     = o1;
    vf_out[2 * NV4 + i4] = o2;
}

// ---------------------------------------------------------------------------
// Fused W+H Gaussian smoothing, single smem buffer: W-pass computed straight
// from gmem (L1-resident re-reads), H-pass from smem. 23KB smem, 1 sync.
// ---------------------------------------------------------------------------
#define TROWS 36
#define IROWS 32
#define NT_HW 5   // 160 / 32

__global__ void __launch_bounds__(256) smoothHW_kernel(const float4* __restrict__ in,
                                                       float4* __restrict__ out) {
    __shared__ float4 s1[TROWS * W4];

    int b  = blockIdx.x;
    int ht = b % NT_HW;
    int d  = (b / NT_HW) % DD;
    int c  = b / (NT_HW * DD);
    int h0 = ht * IROWS;

    const float4* src = in  + (size_t)c * NV4 + (size_t)d * HW4;
    float4*       dst = out + (size_t)c * NV4 + (size_t)d * HW4;
    const float4 z4 = make_float4(0.f, 0.f, 0.f, 0.f);

    for (int t = threadIdx.x; t < TROWS * W4; t += 256) {
        int r  = t / W4;
        int cc = t % W4;
        int hg = h0 - 2 + r;
        float4 o;
        if ((unsigned)hg < HH) {
            const float4* row = src + hg * W4;
            float4 m = __ldg(row + cc);
            float4 l = (cc > 0)      ? __ldg(row + cc - 1) : z4;
            float4 r2 = (cc < W4 - 1) ? __ldg(row + cc + 1) : z4;
            o.x = GW2*l.z + GW1*l.w + GW0*m.x + GW1*m.y + GW2*m.z;
            o.y = GW2*l.w + GW1*m.x + GW0*m.y + GW1*m.z + GW2*m.w;
            o.z = GW2*m.x + GW1*m.y + GW0*m.z + GW1*m.w + GW2*r2.x;
            o.w = GW2*m.y + GW1*m.z + GW0*m.w + GW1*r2.x + GW2*r2.y;
        } else {
            o = z4;
        }
        s1[t] = o;
    }
    __syncthreads();

    for (int t = threadIdx.x; t < IROWS * W4; t += 256) {
        int r  = t / W4 + 2;
        int cc = t % W4;
        float4 a = s1[(r - 2) * W4 + cc];
        float4 b2 = s1[(r - 1) * W4 + cc];
        float4 m = s1[r * W4 + cc];
        float4 e = s1[(r + 1) * W4 + cc];
        float4 f = s1[(r + 2) * W4 + cc];
        float4 o;
        o.x = GW2*(a.x + f.x) + GW1*(b2.x + e.x) + GW0*m.x;
        o.y = GW2*(a.y + f.y) + GW1*(b2.y + e.y) + GW0*m.y;
        o.z = GW2*(a.z + f.z) + GW1*(b2.z + e.z) + GW0*m.z;
        o.w = GW2*(a.w + f.w) + GW1*(b2.w + e.w) + GW0*m.w;
        dst[(h0 + r - 2) * W4 + cc] = o;
    }
}

// ---------------------------------------------------------------------------
// D-axis smoothing, sliding register window (16 outputs/thread — measured best)
// ---------------------------------------------------------------------------
#define DSEG 16
#define NDSEG (DD / DSEG)   // 8

__global__ void __launch_bounds__(256) smoothD_slide(const float4* __restrict__ in,
                                                     float4* __restrict__ out) {
    int gid = blockIdx.x * 256 + threadIdx.x;   // < 3 * NDSEG * HW4
    int col = gid % HW4;
    int seg = (gid / HW4) % NDSEG;
    int c   = gid / (HW4 * NDSEG);
    const float4 z4 = make_float4(0.f, 0.f, 0.f, 0.f);

    const float4* p = in  + (size_t)c * NV4 + col;
    float4*       q = out + (size_t)c * NV4 + col;
    int d0 = seg * DSEG;

    float4 x0 = (d0 - 2 >= 0) ? p[(size_t)(d0 - 2) * HW4] : z4;
    float4 x1 = (d0 - 1 >= 0) ? p[(size_t)(d0 - 1) * HW4] : z4;
    float4 x2 = p[(size_t)d0 * HW4];
    float4 x3 = p[(size_t)(d0 + 1) * HW4];
    float4 x4 = p[(size_t)(d0 + 2) * HW4];

    #pragma unroll
    for (int dd = 0; dd < DSEG; ++dd) {
        int d = d0 + dd;
        float4 o;
        o.x = GW2*(x0.x + x4.x) + GW1*(x1.x + x3.x) + GW0*x2.x;
        o.y = GW2*(x0.y + x4.y) + GW1*(x1.y + x3.y) + GW0*x2.y;
        o.z = GW2*(x0.z + x4.z) + GW1*(x1.z + x3.z) + GW0*x2.z;
        o.w = GW2*(x0.w + x4.w) + GW1*(x1.w + x3.w) + GW0*x2.w;
        q[(size_t)d * HW4] = o;
        x0 = x1; x1 = x2; x2 = x3; x3 = x4;
        x4 = (d + 3 < DD) ? p[(size_t)(d + 3) * HW4] : z4;
    }
}

extern "C" void kernel_launch(void* const* d_in, const int* in_sizes, int n_in,
                              void* d_out, int out_size) {
    const float* mov = (const float*)d_in[0];
    const float4* fix = (const float4*)d_in[1];
    float4* out4 = (float4*)d_out;

    float *vfA, *vfB, *vfC, *sum;
    cudaGetSymbolAddress((void**)&vfA, g_vfA);
    cudaGetSymbolAddress((void**)&vfB, g_vfB);
    cudaGetSymbolAddress((void**)&vfC, g_vfC);
    cudaGetSymbolAddress((void**)&sum, g_sum);

    cudaMemsetAsync(vfA, 0, sizeof(float) * 3 * NV, 0);

    const int blocksN4  = NV4 / 256;                // 3200
    const int blocksHW  = 3 * DD * NT_HW;           // 1920
    const int blocksD   = (3 * NDSEG * HW4) / 256;  // 600

    for (int it = 0; it < NITER; ++it) {
        if (it == 0)
            sum0_kernel<<<blocksN4, 256>>>((const float4*)mov, fix, (float4*)sum);
        else
            warp_kernel4<<<blocksN4, 256>>>(mov, fix, (const float4*)vfA, (float4*)sum);
        force_kernel4<<<blocksN4, 256>>>((const float4*)sum, fix,
                                         (const float4*)vfA, (float4*)vfB);
        smoothHW_kernel<<<blocksHW, 256>>>((const float4*)vfB, (float4*)vfC);
        float4* dst = (it == NITER - 1) ? out4 : (float4*)vfA;
        smoothD_slide<<<blocksD, 256>>>((const float4*)vfC, dst);
    }
}